// round 5
// baseline (speedup 1.0000x reference)
#include <cuda_runtime.h>

#define TSTEPS 50
#define SLEN 400
#define KLEN 50

// ------------------- device scratch -------------------
__device__ float g_pre [64 * SLEN * 512];
__device__ float g_tpre[64 * KLEN * 512];
__device__ float g_x0[1024 * 64];          // [emb(t); mix(t-1)] transposed [K][B]
__device__ float g_xr[1536 * 64];          // [emb(t); h1(t); mix(t)] for readout
__device__ float g_h0T[2][512 * 64];
__device__ float g_h1T[2][512 * 64];
__device__ float g_pIH0[8][1536 * 64];
__device__ float g_pHH0[4][1536 * 64];
__device__ float g_pIH1[4][1536 * 64];
__device__ float g_pHH1[4][1536 * 64];
__device__ float g_pQ [8][512 * 64];       // k-chunks of 64
__device__ float g_pTQ[8][512 * 64];
__device__ float g_pR [12][512 * 64];

__device__ __forceinline__ float sigmoidf_(float x) { return 1.0f / (1.0f + __expf(-x)); }
__device__ __forceinline__ float tanh_fast(float x) {
    float y; asm("tanh.approx.f32 %0, %1;" : "=f"(y) : "f"(x)); return y;
}

// ------------------- GEMM tile: Pout[m0..m0+128][64] = W[m0..,k0..k0+16*nk16] @ Xf -------------------
__device__ __forceinline__ void gemm_tile(const float* __restrict__ W, int ldK, int m0, int k0,
                                          int nk16, float* __restrict__ Pout,
                                          float* Ws, const float* Xf) {
    int tid = threadIdx.x;
    int tm8 = (tid >> 4) * 8, tn4 = (tid & 15) * 4;
    float acc[8][4];
#pragma unroll
    for (int i = 0; i < 8; i++)
#pragma unroll
        for (int j = 0; j < 4; j++) acc[i][j] = 0.f;
    int wrow = tid >> 2, wk = (tid & 3) * 4;
    for (int s = 0; s < nk16 * 16; s += 16) {
#pragma unroll
        for (int p = 0; p < 2; p++) {
            int m = p * 64 + wrow;
            float4 w = *(const float4*)(W + (size_t)(m0 + m) * ldK + k0 + s + wk);
            Ws[(wk + 0) * 132 + m] = w.x; Ws[(wk + 1) * 132 + m] = w.y;
            Ws[(wk + 2) * 132 + m] = w.z; Ws[(wk + 3) * 132 + m] = w.w;
        }
        __syncthreads();
#pragma unroll
        for (int k = 0; k < 16; k++) {
            float4 a0 = *(const float4*)&Ws[k * 132 + tm8];
            float4 a1 = *(const float4*)&Ws[k * 132 + tm8 + 4];
            float4 xv = *(const float4*)&Xf[(s + k) * 64 + tn4];
            float av[8] = {a0.x, a0.y, a0.z, a0.w, a1.x, a1.y, a1.z, a1.w};
            float xw[4] = {xv.x, xv.y, xv.z, xv.w};
#pragma unroll
            for (int i = 0; i < 8; i++)
#pragma unroll
                for (int j = 0; j < 4; j++) acc[i][j] = fmaf(av[i], xw[j], acc[i][j]);
        }
        __syncthreads();
    }
#pragma unroll
    for (int i = 0; i < 8; i++) {
        float4 v = {acc[i][0], acc[i][1], acc[i][2], acc[i][3]};
        *(float4*)(Pout + (size_t)(m0 + tm8 + i) * 64 + tn4) = v;
    }
}

__device__ __forceinline__ void stage_global(float* Xf, const float* __restrict__ Xg,
                                             int k0, int nrows) {
    int tid = threadIdx.x;
    for (int p = 0; p < nrows / 16; p++) {
        int i4 = p * 256 + tid, r = i4 >> 4, c = (i4 & 15) * 4;
        *(float4*)&Xf[r * 64 + c] = *(const float4*)(Xg + (size_t)(k0 + r) * 64 + c);
    }
    __syncthreads();
}

#define GRUACT(comp) { \
    float rg = sigmoidf_(ir.comp + hr.comp); \
    float zg = sigmoidf_(iz.comp + hz.comp); \
    float ng = tanhf(in_.comp + rg * hn.comp); \
    outv.comp = (1.f - zg) * ng + zg * hold4.comp; }

// combine GRU partials into new hidden rows [k0, k0+nrows), store to Xf
__device__ __forceinline__ void stage_comb(float* Xf, int k0, int nrows,
                                           const float* __restrict__ pI, int nI,
                                           const float* __restrict__ pH, int nH,
                                           const float* __restrict__ bi,
                                           const float* __restrict__ bh,
                                           const float* __restrict__ hold) {
    const int CH = 1536 * 64;
    int tid = threadIdx.x;
    for (int p = 0; p < nrows / 16; p++) {
        int i4 = p * 256 + tid, r = i4 >> 4, c = (i4 & 15) * 4;
        int j = k0 + r;
        float biR = bi[j], biZ = bi[j + 512], biN = bi[j + 1024];
        float bhR = bh[j], bhZ = bh[j + 512], bhN = bh[j + 1024];
        float4 ir = {biR, biR, biR, biR};
        float4 iz = {biZ, biZ, biZ, biZ};
        float4 in_ = {biN, biN, biN, biN};
        float4 hr = {bhR, bhR, bhR, bhR};
        float4 hz = {bhZ, bhZ, bhZ, bhZ};
        float4 hn = {bhN, bhN, bhN, bhN};
        for (int kc = 0; kc < nI; kc++) {
            const float* p0 = pI + (size_t)kc * CH;
            float4 a = *(const float4*)(p0 + (size_t)j * 64 + c);
            float4 b2 = *(const float4*)(p0 + (size_t)(j + 512) * 64 + c);
            float4 d = *(const float4*)(p0 + (size_t)(j + 1024) * 64 + c);
            ir.x += a.x; ir.y += a.y; ir.z += a.z; ir.w += a.w;
            iz.x += b2.x; iz.y += b2.y; iz.z += b2.z; iz.w += b2.w;
            in_.x += d.x; in_.y += d.y; in_.z += d.z; in_.w += d.w;
        }
        for (int kc = 0; kc < nH; kc++) {
            const float* p0 = pH + (size_t)kc * CH;
            float4 e = *(const float4*)(p0 + (size_t)j * 64 + c);
            float4 f = *(const float4*)(p0 + (size_t)(j + 512) * 64 + c);
            float4 g = *(const float4*)(p0 + (size_t)(j + 1024) * 64 + c);
            hr.x += e.x; hr.y += e.y; hr.z += e.z; hr.w += e.w;
            hz.x += f.x; hz.y += f.y; hz.z += f.z; hz.w += f.w;
            hn.x += g.x; hn.y += g.y; hn.z += g.z; hn.w += g.w;
        }
        float4 hold4 = *(const float4*)(hold + (size_t)j * 64 + c);
        float4 outv;
        GRUACT(x) GRUACT(y) GRUACT(z) GRUACT(w)
        *(float4*)&Xf[r * 64 + c] = outv;
    }
    __syncthreads();
}

// ------------------- init -------------------
__global__ void kInit(const int* __restrict__ tgt, const float* __restrict__ hidden,
                      const float* __restrict__ mix_init, const float* __restrict__ embt) {
    int i = blockIdx.x * 256 + threadIdx.x;  // 32768
    int b = i >> 9, d = i & 511;
    g_h0T[0][d * 64 + b] = hidden[i];
    g_h1T[0][d * 64 + b] = hidden[32768 + i];
    g_x0[(512 + d) * 64 + b] = mix_init[i];
    int tok = tgt[b];
    g_x0[d * 64 + b] = embt[(size_t)tok * 512 + d];
}

// ------------------- pre = ctx @ W^T + b (proven R2 kernel) -------------------
__global__ void pre_gemm(const float* __restrict__ context, const float* __restrict__ tcontext,
                         const float* __restrict__ preW, const float* __restrict__ preB,
                         const float* __restrict__ tpreW, const float* __restrict__ tpreB) {
    __shared__ float Ws[32][132];
    __shared__ float Xs[32][64];
    int l = blockIdx.x;
    const float *ctx, *W, *bias; float* out; int L;
    if (l < SLEN) { ctx = context;  W = preW;  bias = preB;  out = g_pre;  L = SLEN; }
    else { l -= SLEN; ctx = tcontext; W = tpreW; bias = tpreB; out = g_tpre; L = KLEN; }
    int m0 = blockIdx.y * 128;
    int tid = threadIdx.x;
    int tm8 = (tid >> 4) * 8, tn4 = (tid & 15) * 4;
    float acc[8][4];
#pragma unroll
    for (int i = 0; i < 8; i++)
#pragma unroll
        for (int j = 0; j < 4; j++) acc[i][j] = 0.f;
    int wrow = tid >> 3, wk = (tid & 7) * 4;
    int xb = tid >> 2, xk = (tid & 3) * 8;
    const float* xbase = ctx + (size_t)l * 64 * 512;
    for (int s = 0; s < 512; s += 32) {
#pragma unroll
        for (int p = 0; p < 4; p++) {
            int m = p * 32 + wrow;
            float4 w = *(const float4*)(W + (size_t)(m0 + m) * 512 + s + wk);
            Ws[wk + 0][m] = w.x; Ws[wk + 1][m] = w.y; Ws[wk + 2][m] = w.z; Ws[wk + 3][m] = w.w;
        }
        {
            const float* cp = xbase + (size_t)xb * 512 + s + xk;
            float4 c0 = *(const float4*)(cp);
            float4 c1 = *(const float4*)(cp + 4);
            Xs[xk + 0][xb] = c0.x; Xs[xk + 1][xb] = c0.y; Xs[xk + 2][xb] = c0.z; Xs[xk + 3][xb] = c0.w;
            Xs[xk + 4][xb] = c1.x; Xs[xk + 5][xb] = c1.y; Xs[xk + 6][xb] = c1.z; Xs[xk + 7][xb] = c1.w;
        }
        __syncthreads();
#pragma unroll 8
        for (int k = 0; k < 32; k++) {
            float4 a0 = *(const float4*)&Ws[k][tm8];
            float4 a1 = *(const float4*)&Ws[k][tm8 + 4];
            float4 xv = *(const float4*)&Xs[k][tn4];
            float av[8] = {a0.x, a0.y, a0.z, a0.w, a1.x, a1.y, a1.z, a1.w};
            float xw[4] = {xv.x, xv.y, xv.z, xv.w};
#pragma unroll
            for (int i = 0; i < 8; i++)
#pragma unroll
                for (int j = 0; j < 4; j++) acc[i][j] = fmaf(av[i], xw[j], acc[i][j]);
        }
        __syncthreads();
    }
#pragma unroll
    for (int jj = 0; jj < 4; jj++) {
        int b = tn4 + jj;
        float* op = out + ((size_t)b * L + l) * 512 + m0 + tm8;
        float4 v0 = {acc[0][jj] + bias[m0 + tm8 + 0], acc[1][jj] + bias[m0 + tm8 + 1],
                     acc[2][jj] + bias[m0 + tm8 + 2], acc[3][jj] + bias[m0 + tm8 + 3]};
        float4 v1 = {acc[4][jj] + bias[m0 + tm8 + 4], acc[5][jj] + bias[m0 + tm8 + 5],
                     acc[6][jj] + bias[m0 + tm8 + 6], acc[7][jj] + bias[m0 + tm8 + 7]};
        *(float4*)(op) = v0;
        *(float4*)(op + 4) = v1;
    }
}

// ------------------- kA: GRU0 GEMMs (144 blocks) -------------------
__global__ void __launch_bounds__(256)
kA(const float* __restrict__ W_ih0, const float* __restrict__ W_hh0, int t) {
    __shared__ float Ws[16 * 132];
    __shared__ float Xf[128 * 64];
    int bid = blockIdx.x;
    int po = t & 1;
    if (bid < 96) {
        int mt = bid % 12, kc = bid / 12;
        stage_global(Xf, g_x0, kc * 128, 128);
        gemm_tile(W_ih0, 1024, mt * 128, kc * 128, 8, g_pIH0[kc], Ws, Xf);
    } else {
        int id = bid - 96, mt = id % 12, kc = id / 12;
        stage_global(Xf, g_h0T[po], kc * 128, 128);
        gemm_tile(W_hh0, 512, mt * 128, kc * 128, 8, g_pHH0[kc], Ws, Xf);
    }
}

// ------------------- kC: GRU1 GEMMs with inline act0 (96 blocks) -------------------
__global__ void __launch_bounds__(256)
kC(const float* __restrict__ W_ih1, const float* __restrict__ W_hh1,
   const float* __restrict__ b_ih0, const float* __restrict__ b_hh0, int t) {
    __shared__ float Ws[16 * 132];
    __shared__ float Xf[128 * 64];
    int bid = blockIdx.x, tid = threadIdx.x;
    int po = t & 1, pn = po ^ 1;
    if (bid < 48) {
        int mt = bid % 12, kc = bid / 12;
        stage_comb(Xf, kc * 128, 128, (const float*)g_pIH0, 8, (const float*)g_pHH0, 4,
                   b_ih0, b_hh0, g_h0T[po]);
        if (mt == 0) {
            for (int p = 0; p < 8; p++) {
                int i4 = p * 256 + tid, r = i4 >> 4, c = (i4 & 15) * 4;
                int j = kc * 128 + r;
                *(float4*)(g_h0T[pn] + (size_t)j * 64 + c) = *(const float4*)&Xf[r * 64 + c];
            }
        }
        gemm_tile(W_ih1, 512, mt * 128, kc * 128, 8, g_pIH1[kc], Ws, Xf);
    } else {
        int id = bid - 48, mt = id % 12, kc = id / 12;
        stage_global(Xf, g_h1T[po], kc * 128, 128);
        gemm_tile(W_hh1, 512, mt * 128, kc * 128, 8, g_pHH1[kc], Ws, Xf);
    }
}

// ------------------- kD: q/tq GEMMs (inline act1) + readout GEMM of t-1 (112 blocks) -------------------
__global__ void __launch_bounds__(256)
kD(const float* __restrict__ qW, const float* __restrict__ tqW,
   const float* __restrict__ RW,
   const float* __restrict__ b_ih1, const float* __restrict__ b_hh1, int t) {
    __shared__ float Ws[16 * 132];
    __shared__ float Xf[128 * 64];
    int bid = blockIdx.x, tid = threadIdx.x;
    int po = t & 1, pn = po ^ 1;
    if (bid < 64) {
        int mat = bid >> 5, id = bid & 31, mt = id & 3, kc = id >> 2;  // kc in [0,8), 64-row chunks
        stage_comb(Xf, kc * 64, 64, (const float*)g_pIH1, 4, (const float*)g_pHH1, 4,
                   b_ih1, b_hh1, g_h1T[po]);
        if (mat == 0 && mt == 0) {
            for (int p = 0; p < 4; p++) {
                int i4 = p * 256 + tid, r = i4 >> 4, c = (i4 & 15) * 4;
                int j = kc * 64 + r;
                *(float4*)(g_h1T[pn] + (size_t)j * 64 + c) = *(const float4*)&Xf[r * 64 + c];
            }
        }
        gemm_tile(mat ? tqW : qW, 512, mt * 128, kc * 64, 4,
                  mat ? g_pTQ[kc] : g_pQ[kc], Ws, Xf);
    } else if (t > 0) {
        int id = bid - 64, mt = id % 4, kc = id / 4;   // kc in [0,12)
        stage_global(Xf, g_xr, kc * 128, 128);
        gemm_tile(RW, 1536, mt * 128, kc * 128, 8, g_pR[kc], Ws, Xf);
    }
}

// ------------------- kE: attention + gate + softmax + ctxmix + copies + actD(t-1) -------------------
__global__ void __launch_bounds__(512)
kE(const float* __restrict__ context, const float* __restrict__ tcontext,
   const float* __restrict__ smask, const float* __restrict__ tmask,
   const float* __restrict__ av, const float* __restrict__ tav,
   const float* __restrict__ gW, const float* __restrict__ gb,
   const float* __restrict__ Rb, const int* __restrict__ tgt,
   const float* __restrict__ embt,
   float* __restrict__ go, float* __restrict__ attn, float* __restrict__ tattn,
   float* __restrict__ gatev, int t) {
    int bid = blockIdx.x, tid = threadIdx.x;
    int pn = (t & 1) ^ 1;

    if (bid >= 64) {   // actD for step t-1 (4 blocks x 512 threads x 8 outputs)
        if (t > 0) {
            int id = bid - 64;
            for (int p = 0; p < 8; p++) {
                int i = id * 4096 + p * 512 + tid;
                int u = i >> 6, b = i & 63;
                int j0 = 2 * u, j1 = 2 * u + 1;
                float r0 = Rb[j0], r1 = Rb[j1];
#pragma unroll
                for (int kc = 0; kc < 12; kc++) {
                    r0 += g_pR[kc][(size_t)j0 * 64 + b];
                    r1 += g_pR[kc][(size_t)j1 * 64 + b];
                }
                go[(size_t)(t - 1) * 16384 + b * 256 + u] = fmaxf(r0, r1);
            }
        }
        return;
    }

    int b = bid;
    __shared__ float qs[512], tqs[512], vs[512], tvs[512], es[SLEN], tes[56], sred[16];
    int warp = tid >> 5, lane = tid & 31;
    int d = tid;

    // stage q/tq (sum 8 partials), v vectors; copy h1 and emb into g_xr; gate partial
    float s1 = 0.f, s2 = 0.f;
#pragma unroll
    for (int kc = 0; kc < 8; kc++) {
        s1 += g_pQ[kc][(size_t)d * 64 + b];
        s2 += g_pTQ[kc][(size_t)d * 64 + b];
    }
    qs[d] = s1; tqs[d] = s2;
    vs[d] = av[d]; tvs[d] = tav[d];
    float h1v = g_h1T[pn][(size_t)d * 64 + b];
    g_xr[(size_t)(512 + d) * 64 + b] = h1v;          // h1(t) for readout
    g_xr[(size_t)d * 64 + b] = g_x0[(size_t)d * 64 + b];  // emb(t) for readout
    float gv = h1v * gW[d];
#pragma unroll
    for (int o = 16; o; o >>= 1) gv += __shfl_xor_sync(0xffffffffu, gv, o);
    if (lane == 0) sred[warp] = gv;
    __syncthreads();
    float gsum = 0.f;
#pragma unroll
    for (int w = 0; w < 16; w++) gsum += sred[w];
    float gate = sigmoidf_(gsum + gb[0]);
    if (tid == 0) gatev[t * 64 + b] = gate;
    __syncthreads();

    // energies
    for (int l = warp; l < SLEN; l += 16) {
        const float* pr = g_pre + ((size_t)b * SLEN + l) * 512;
        float e = 0.f;
#pragma unroll
        for (int c = 0; c < 4; c++) {
            int a = c * 128 + lane * 4;
            float4 p = *(const float4*)(pr + a);
            float4 q4 = *(const float4*)(qs + a);
            float4 v4 = *(const float4*)(vs + a);
            e += tanh_fast(p.x + q4.x) * v4.x;
            e += tanh_fast(p.y + q4.y) * v4.y;
            e += tanh_fast(p.z + q4.z) * v4.z;
            e += tanh_fast(p.w + q4.w) * v4.w;
        }
#pragma unroll
        for (int o = 16; o; o >>= 1) e += __shfl_xor_sync(0xffffffffu, e, o);
        if (lane == 0) es[l] = (smask[b * SLEN + l] > 0.5f) ? -1e6f : e;
    }
    for (int l = warp; l < KLEN; l += 16) {
        const float* pr = g_tpre + ((size_t)b * KLEN + l) * 512;
        float e = 0.f;
#pragma unroll
        for (int c = 0; c < 4; c++) {
            int a = c * 128 + lane * 4;
            float4 p = *(const float4*)(pr + a);
            float4 q4 = *(const float4*)(tqs + a);
            float4 v4 = *(const float4*)(tvs + a);
            e += tanh_fast(p.x + q4.x) * v4.x;
            e += tanh_fast(p.y + q4.y) * v4.y;
            e += tanh_fast(p.z + q4.z) * v4.z;
            e += tanh_fast(p.w + q4.w) * v4.w;
        }
#pragma unroll
        for (int o = 16; o; o >>= 1) e += __shfl_xor_sync(0xffffffffu, e, o);
        if (lane == 0) tes[l] = (tmask[b * KLEN + l] > 0.5f) ? -1e6f : e;
    }
    __syncthreads();

    // softmax over src (400)
    float m = (tid < SLEN) ? es[tid] : -3.4e38f;
#pragma unroll
    for (int o = 16; o; o >>= 1) m = fmaxf(m, __shfl_xor_sync(0xffffffffu, m, o));
    if (lane == 0) sred[warp] = m;
    __syncthreads();
    float bm = sred[0];
#pragma unroll
    for (int w = 1; w < 16; w++) bm = fmaxf(bm, sred[w]);
    __syncthreads();
    float ex = (tid < SLEN) ? __expf(es[tid] - bm) : 0.f;
    float ssum = ex;
#pragma unroll
    for (int o = 16; o; o >>= 1) ssum += __shfl_xor_sync(0xffffffffu, ssum, o);
    if (lane == 0) sred[warp] = ssum;
    __syncthreads();
    float bs = 0.f;
#pragma unroll
    for (int w = 0; w < 16; w++) bs += sred[w];
    float inv = 1.0f / bs;
    __syncthreads();
    if (tid < SLEN) {
        float pv = ex * inv;
        es[tid] = pv;
        attn[(size_t)t * 64 * SLEN + (size_t)b * SLEN + tid] = pv;
    }
    __syncthreads();

    // softmax over topic (50)
    float tm_ = (tid < KLEN) ? tes[tid] : -3.4e38f;
#pragma unroll
    for (int o = 16; o; o >>= 1) tm_ = fmaxf(tm_, __shfl_xor_sync(0xffffffffu, tm_, o));
    if (lane == 0) sred[warp] = tm_;
    __syncthreads();
    float tbm = sred[0];
#pragma unroll
    for (int w = 1; w < 16; w++) tbm = fmaxf(tbm, sred[w]);
    __syncthreads();
    float tex = (tid < KLEN) ? __expf(tes[tid] - tbm) : 0.f;
    float tssum = tex;
#pragma unroll
    for (int o = 16; o; o >>= 1) tssum += __shfl_xor_sync(0xffffffffu, tssum, o);
    if (lane == 0) sred[warp] = tssum;
    __syncthreads();
    float tbs = 0.f;
#pragma unroll
    for (int w = 0; w < 16; w++) tbs += sred[w];
    float tinv = 1.0f / tbs;
    __syncthreads();
    if (tid < KLEN) {
        float pv = tex * tinv;
        tes[tid] = pv;
        tattn[(size_t)t * 64 * KLEN + (size_t)b * KLEN + tid] = pv;
    }
    __syncthreads();

    // ctxmix: thread d computes mixed context element
    const float* cb = context + (size_t)b * 512 + d;
    float c = 0.f;
#pragma unroll 8
    for (int l = 0; l < SLEN; l++) c += es[l] * cb[(size_t)l * 64 * 512];
    const float* tcb = tcontext + (size_t)b * 512 + d;
    float tc = 0.f;
#pragma unroll 10
    for (int l = 0; l < KLEN; l++) tc += tes[l] * tcb[(size_t)l * 64 * 512];
    float mixv = gate * c + (1.f - gate) * tc;
    g_x0[(size_t)(512 + d) * 64 + b] = mixv;     // mix for next GRU0 input
    g_xr[(size_t)(1024 + d) * 64 + b] = mixv;    // mix for this step's readout

    // emb prefetch for step t+1 (overwrites g_x0 emb AFTER it was copied to g_xr above)
    if (t + 1 < TSTEPS) {
        int tok = tgt[(t + 1) * 64 + b];
        g_x0[(size_t)d * 64 + b] = embt[(size_t)tok * 512 + d];
    }
}

// ------------------- kR: readout GEMM for t=49 -------------------
__global__ void __launch_bounds__(256)
kR(const float* __restrict__ RW) {
    __shared__ float Ws[16 * 132];
    __shared__ float Xf[128 * 64];
    int bid = blockIdx.x;
    int mt = bid % 4, kc = bid / 4;
    stage_global(Xf, g_xr, kc * 128, 128);
    gemm_tile(RW, 1536, mt * 128, kc * 128, 8, g_pR[kc], Ws, Xf);
}

// ------------------- kFin: actD(49) + final state copies -------------------
__global__ void __launch_bounds__(256)
kFin(const float* __restrict__ Rb, float* __restrict__ go,
     float* __restrict__ hf, float* __restrict__ mixf) {
    int bid = blockIdx.x, tid = threadIdx.x;
    if (bid < 4) {
        for (int p = 0; p < 16; p++) {
            int i = bid * 4096 + p * 256 + tid;
            int u = i >> 6, b = i & 63;
            int j0 = 2 * u, j1 = 2 * u + 1;
            float r0 = Rb[j0], r1 = Rb[j1];
#pragma unroll
            for (int kc = 0; kc < 12; kc++) {
                r0 += g_pR[kc][(size_t)j0 * 64 + b];
                r1 += g_pR[kc][(size_t)j1 * 64 + b];
            }
            go[(size_t)49 * 16384 + b * 256 + u] = fmaxf(r0, r1);
        }
    } else {
        for (int i = (bid - 4) * 256 + tid; i < 32768; i += 16 * 256) {
            int b = i >> 9, d = i & 511;
            hf[i] = g_h0T[0][d * 64 + b];           // after t=49 (po=1) new state is index 0
            hf[32768 + i] = g_h1T[0][d * 64 + b];
            mixf[i] = g_x0[(512 + d) * 64 + b];
        }
    }
}

// ------------------- launch -------------------
extern "C" void kernel_launch(void* const* d_in, const int* in_sizes, int n_in,
                              void* d_out, int out_size) {
    const int*   tgt      = (const int*)d_in[0];
    const float* hidden   = (const float*)d_in[1];
    const float* context  = (const float*)d_in[2];
    const float* smask    = (const float*)d_in[3];
    const float* tcontext = (const float*)d_in[4];
    const float* tmask    = (const float*)d_in[5];
    const float* mix_init = (const float*)d_in[6];
    const float* embt     = (const float*)d_in[7];
    const float* W_ih0    = (const float*)d_in[8];
    const float* W_hh0    = (const float*)d_in[9];
    const float* b_ih0    = (const float*)d_in[10];
    const float* b_hh0    = (const float*)d_in[11];
    const float* W_ih1    = (const float*)d_in[12];
    const float* W_hh1    = (const float*)d_in[13];
    const float* b_ih1    = (const float*)d_in[14];
    const float* b_hh1    = (const float*)d_in[15];
    const float* preW     = (const float*)d_in[16];
    const float* preB     = (const float*)d_in[17];
    const float* qW       = (const float*)d_in[18];
    const float* av       = (const float*)d_in[19];
    const float* tpreW    = (const float*)d_in[20];
    const float* tpreB    = (const float*)d_in[21];
    const float* tqW      = (const float*)d_in[22];
    const float* tav      = (const float*)d_in[23];
    const float* RW       = (const float*)d_in[24];
    const float* Rb       = (const float*)d_in[25];
    const float* gW       = (const float*)d_in[26];
    const float* gb       = (const float*)d_in[27];

    float* out   = (float*)d_out;
    float* go    = out;                                   // [T,B,256]
    float* hf    = go + (size_t)TSTEPS * 64 * 256;        // [2,B,D]
    float* attn  = hf + 2 * 64 * 512;                     // [T,B,S]
    float* tattn = attn + (size_t)TSTEPS * 64 * SLEN;     // [T,B,K]
    float* mixf  = tattn + (size_t)TSTEPS * 64 * KLEN;    // [B,D]
    float* gatev = mixf + 64 * 512;                       // [T,B,1]

    kInit<<<128, 256>>>(tgt, hidden, mix_init, embt);
    pre_gemm<<<dim3(SLEN + KLEN, 4), 256>>>(context, tcontext, preW, preB, tpreW, tpreB);

    for (int t = 0; t < TSTEPS; t++) {
        kA<<<144, 256>>>(W_ih0, W_hh0, t);
        kC<<<96, 256>>>(W_ih1, W_hh1, b_ih0, b_hh0, t);
        kD<<<112, 256>>>(qW, tqW, RW, b_ih1, b_hh1, t);
        kE<<<68, 512>>>(context, tcontext, smask, tmask, av, tav, gW, gb, Rb,
                        tgt, embt, go, attn, tattn, gatev, t);
    }
    kR<<<48, 256>>>(RW);
    kFin<<<20, 256>>>(Rb, go, hf, mixf);
}

// round 8
// speedup vs baseline: 1.3594x; 1.3594x over previous
#include <cuda_runtime.h>

#define TSTEPS 50
#define SLEN 400
#define KLEN 50

// ------------------- device scratch -------------------
__device__ float g_pre [64 * SLEN * 512];
__device__ float g_tpre[64 * KLEN * 512];
__device__ float g_x0[1024 * 64];          // [emb(t); mix(t-1)] transposed [K][B]
__device__ float g_xr[1536 * 64];          // [emb(t); h1(t); mix(t)] for readout
__device__ float g_h0T[2][512 * 64];
__device__ float g_h1T[2][512 * 64];
__device__ float g_pIH0[8][1536 * 64];
__device__ float g_pHH0[4][1536 * 64];
__device__ float g_pIH1[4][1536 * 64];
__device__ float g_pHH1[4][1536 * 64];
__device__ float g_pQ [8][512 * 64];       // k-chunks of 64
__device__ float g_pTQ[8][512 * 64];
__device__ float g_pR [12][512 * 64];

__device__ __forceinline__ float sigmoidf_(float x) { return 1.0f / (1.0f + __expf(-x)); }
__device__ __forceinline__ float tanh_fast(float x) {
    float y; asm("tanh.approx.f32 %0, %1;" : "=f"(y) : "f"(x)); return y;
}

// ------------------- GEMM tile -------------------
__device__ __forceinline__ void gemm_tile(const float* __restrict__ W, int ldK, int m0, int k0,
                                          int nk16, float* __restrict__ Pout,
                                          float* Ws, const float* Xf) {
    int tid = threadIdx.x;
    int tm8 = (tid >> 4) * 8, tn4 = (tid & 15) * 4;
    float acc[8][4];
#pragma unroll
    for (int i = 0; i < 8; i++)
#pragma unroll
        for (int j = 0; j < 4; j++) acc[i][j] = 0.f;
    int wrow = tid >> 2, wk = (tid & 3) * 4;
    for (int s = 0; s < nk16 * 16; s += 16) {
#pragma unroll
        for (int p = 0; p < 2; p++) {
            int m = p * 64 + wrow;
            float4 w = *(const float4*)(W + (size_t)(m0 + m) * ldK + k0 + s + wk);
            Ws[(wk + 0) * 132 + m] = w.x; Ws[(wk + 1) * 132 + m] = w.y;
            Ws[(wk + 2) * 132 + m] = w.z; Ws[(wk + 3) * 132 + m] = w.w;
        }
        __syncthreads();
#pragma unroll
        for (int k = 0; k < 16; k++) {
            float4 a0 = *(const float4*)&Ws[k * 132 + tm8];
            float4 a1 = *(const float4*)&Ws[k * 132 + tm8 + 4];
            float4 xv = *(const float4*)&Xf[(s + k) * 64 + tn4];
            float av[8] = {a0.x, a0.y, a0.z, a0.w, a1.x, a1.y, a1.z, a1.w};
            float xw[4] = {xv.x, xv.y, xv.z, xv.w};
#pragma unroll
            for (int i = 0; i < 8; i++)
#pragma unroll
                for (int j = 0; j < 4; j++) acc[i][j] = fmaf(av[i], xw[j], acc[i][j]);
        }
        __syncthreads();
    }
#pragma unroll
    for (int i = 0; i < 8; i++) {
        float4 v = {acc[i][0], acc[i][1], acc[i][2], acc[i][3]};
        *(float4*)(Pout + (size_t)(m0 + tm8 + i) * 64 + tn4) = v;
    }
}

__device__ __forceinline__ void stage_global(float* Xf, const float* __restrict__ Xg,
                                             int k0, int nrows) {
    int tid = threadIdx.x;
    for (int p = 0; p < nrows / 16; p++) {
        int i4 = p * 256 + tid, r = i4 >> 4, c = (i4 & 15) * 4;
        *(float4*)&Xf[r * 64 + c] = *(const float4*)(Xg + (size_t)(k0 + r) * 64 + c);
    }
    __syncthreads();
}

#define GRUACT(comp) { \
    float rg = sigmoidf_(ir.comp + hr.comp); \
    float zg = sigmoidf_(iz.comp + hz.comp); \
    float ng = tanhf(in_.comp + rg * hn.comp); \
    outv.comp = (1.f - zg) * ng + zg * hold4.comp; }

// ------------------- init -------------------
__global__ void kInit(const int* __restrict__ tgt, const float* __restrict__ hidden,
                      const float* __restrict__ mix_init, const float* __restrict__ embt) {
    int i = blockIdx.x * 256 + threadIdx.x;  // 32768
    int b = i >> 9, d = i & 511;
    g_h0T[0][d * 64 + b] = hidden[i];
    g_h1T[0][d * 64 + b] = hidden[32768 + i];
    g_x0[(512 + d) * 64 + b] = mix_init[i];
    int tok = tgt[b];
    g_x0[d * 64 + b] = embt[(size_t)tok * 512 + d];
}

// ------------------- pre = ctx @ W^T + b (proven) -------------------
__global__ void pre_gemm(const float* __restrict__ context, const float* __restrict__ tcontext,
                         const float* __restrict__ preW, const float* __restrict__ preB,
                         const float* __restrict__ tpreW, const float* __restrict__ tpreB) {
    __shared__ float Ws[32][132];
    __shared__ float Xs[32][64];
    int l = blockIdx.x;
    const float *ctx, *W, *bias; float* out; int L;
    if (l < SLEN) { ctx = context;  W = preW;  bias = preB;  out = g_pre;  L = SLEN; }
    else { l -= SLEN; ctx = tcontext; W = tpreW; bias = tpreB; out = g_tpre; L = KLEN; }
    int m0 = blockIdx.y * 128;
    int tid = threadIdx.x;
    int tm8 = (tid >> 4) * 8, tn4 = (tid & 15) * 4;
    float acc[8][4];
#pragma unroll
    for (int i = 0; i < 8; i++)
#pragma unroll
        for (int j = 0; j < 4; j++) acc[i][j] = 0.f;
    int wrow = tid >> 3, wk = (tid & 7) * 4;
    int xb = tid >> 2, xk = (tid & 3) * 8;
    const float* xbase = ctx + (size_t)l * 64 * 512;
    for (int s = 0; s < 512; s += 32) {
#pragma unroll
        for (int p = 0; p < 4; p++) {
            int m = p * 32 + wrow;
            float4 w = *(const float4*)(W + (size_t)(m0 + m) * 512 + s + wk);
            Ws[wk + 0][m] = w.x; Ws[wk + 1][m] = w.y; Ws[wk + 2][m] = w.z; Ws[wk + 3][m] = w.w;
        }
        {
            const float* cp = xbase + (size_t)xb * 512 + s + xk;
            float4 c0 = *(const float4*)(cp);
            float4 c1 = *(const float4*)(cp + 4);
            Xs[xk + 0][xb] = c0.x; Xs[xk + 1][xb] = c0.y; Xs[xk + 2][xb] = c0.z; Xs[xk + 3][xb] = c0.w;
            Xs[xk + 4][xb] = c1.x; Xs[xk + 5][xb] = c1.y; Xs[xk + 6][xb] = c1.z; Xs[xk + 7][xb] = c1.w;
        }
        __syncthreads();
#pragma unroll 8
        for (int k = 0; k < 32; k++) {
            float4 a0 = *(const float4*)&Ws[k][tm8];
            float4 a1 = *(const float4*)&Ws[k][tm8 + 4];
            float4 xv = *(const float4*)&Xs[k][tn4];
            float av[8] = {a0.x, a0.y, a0.z, a0.w, a1.x, a1.y, a1.z, a1.w};
            float xw[4] = {xv.x, xv.y, xv.z, xv.w};
#pragma unroll
            for (int i = 0; i < 8; i++)
#pragma unroll
                for (int j = 0; j < 4; j++) acc[i][j] = fmaf(av[i], xw[j], acc[i][j]);
        }
        __syncthreads();
    }
#pragma unroll
    for (int jj = 0; jj < 4; jj++) {
        int b = tn4 + jj;
        float* op = out + ((size_t)b * L + l) * 512 + m0 + tm8;
        float4 v0 = {acc[0][jj] + bias[m0 + tm8 + 0], acc[1][jj] + bias[m0 + tm8 + 1],
                     acc[2][jj] + bias[m0 + tm8 + 2], acc[3][jj] + bias[m0 + tm8 + 3]};
        float4 v1 = {acc[4][jj] + bias[m0 + tm8 + 4], acc[5][jj] + bias[m0 + tm8 + 5],
                     acc[6][jj] + bias[m0 + tm8 + 6], acc[7][jj] + bias[m0 + tm8 + 7]};
        *(float4*)(op) = v0;
        *(float4*)(op + 4) = v1;
    }
}

// ------------------- kA: GRU0 GEMMs (144 blocks) -------------------
__global__ void __launch_bounds__(256)
kA(const float* __restrict__ W_ih0, const float* __restrict__ W_hh0, int t) {
    __shared__ float Ws[16 * 132];
    __shared__ float Xf[128 * 64];
    int bid = blockIdx.x;
    int po = t & 1;
    if (bid < 96) {
        int mt = bid % 12, kc = bid / 12;
        stage_global(Xf, g_x0, kc * 128, 128);
        gemm_tile(W_ih0, 1024, mt * 128, kc * 128, 8, g_pIH0[kc], Ws, Xf);
    } else {
        int id = bid - 96, mt = id % 12, kc = id / 12;
        stage_global(Xf, g_h0T[po], kc * 128, 128);
        gemm_tile(W_hh0, 512, mt * 128, kc * 128, 8, g_pHH0[kc], Ws, Xf);
    }
}

// ------------------- generic GRU activation combine (one pass, 32 blocks) -------------------
__device__ __forceinline__ void act_combine(const float* __restrict__ pI, int nI,
                                            const float* __restrict__ pH, int nH,
                                            const float* __restrict__ bi,
                                            const float* __restrict__ bh,
                                            const float* __restrict__ hold,
                                            float* __restrict__ hnew, float* __restrict__ hnew2) {
    const int CH = 1536 * 64;
    int i4 = blockIdx.x * 256 + threadIdx.x;   // 8192 float4 slots: 512 rows x 16
    int j = i4 >> 4, c = (i4 & 15) * 4;
    float biR = bi[j], biZ = bi[j + 512], biN = bi[j + 1024];
    float bhR = bh[j], bhZ = bh[j + 512], bhN = bh[j + 1024];
    float4 ir = {biR, biR, biR, biR};
    float4 iz = {biZ, biZ, biZ, biZ};
    float4 in_ = {biN, biN, biN, biN};
    float4 hr = {bhR, bhR, bhR, bhR};
    float4 hz = {bhZ, bhZ, bhZ, bhZ};
    float4 hn = {bhN, bhN, bhN, bhN};
    for (int kc = 0; kc < nI; kc++) {
        const float* p0 = pI + (size_t)kc * CH;
        float4 a = *(const float4*)(p0 + (size_t)j * 64 + c);
        float4 b2 = *(const float4*)(p0 + (size_t)(j + 512) * 64 + c);
        float4 d = *(const float4*)(p0 + (size_t)(j + 1024) * 64 + c);
        ir.x += a.x; ir.y += a.y; ir.z += a.z; ir.w += a.w;
        iz.x += b2.x; iz.y += b2.y; iz.z += b2.z; iz.w += b2.w;
        in_.x += d.x; in_.y += d.y; in_.z += d.z; in_.w += d.w;
    }
    for (int kc = 0; kc < nH; kc++) {
        const float* p0 = pH + (size_t)kc * CH;
        float4 e = *(const float4*)(p0 + (size_t)j * 64 + c);
        float4 f = *(const float4*)(p0 + (size_t)(j + 512) * 64 + c);
        float4 g = *(const float4*)(p0 + (size_t)(j + 1024) * 64 + c);
        hr.x += e.x; hr.y += e.y; hr.z += e.z; hr.w += e.w;
        hz.x += f.x; hz.y += f.y; hz.z += f.z; hz.w += f.w;
        hn.x += g.x; hn.y += g.y; hn.z += g.z; hn.w += g.w;
    }
    float4 hold4 = *(const float4*)(hold + (size_t)j * 64 + c);
    float4 outv;
    GRUACT(x) GRUACT(y) GRUACT(z) GRUACT(w)
    *(float4*)(hnew + (size_t)j * 64 + c) = outv;
    if (hnew2) *(float4*)(hnew2 + (size_t)j * 64 + c) = outv;
}

__global__ void __launch_bounds__(256)
kAct0(const float* __restrict__ b_ih0, const float* __restrict__ b_hh0, int t) {
    int po = t & 1, pn = po ^ 1;
    act_combine((const float*)g_pIH0, 8, (const float*)g_pHH0, 4,
                b_ih0, b_hh0, g_h0T[po], g_h0T[pn], nullptr);
}

__global__ void __launch_bounds__(256)
kAct1(const float* __restrict__ b_ih1, const float* __restrict__ b_hh1, int t) {
    int po = t & 1, pn = po ^ 1;
    act_combine((const float*)g_pIH1, 4, (const float*)g_pHH1, 4,
                b_ih1, b_hh1, g_h1T[po], g_h1T[pn], g_xr + 512 * 64);
}

// ------------------- kB: GRU1 GEMMs + readout GEMM of t-1 (144 blocks) -------------------
__global__ void __launch_bounds__(256)
kB(const float* __restrict__ W_ih1, const float* __restrict__ W_hh1,
   const float* __restrict__ RW, int t) {
    __shared__ float Ws[16 * 132];
    __shared__ float Xf[128 * 64];
    int bid = blockIdx.x;
    int po = t & 1, pn = po ^ 1;
    if (bid < 48) {
        int mt = bid % 12, kc = bid / 12;
        stage_global(Xf, g_h0T[pn], kc * 128, 128);
        gemm_tile(W_ih1, 512, mt * 128, kc * 128, 8, g_pIH1[kc], Ws, Xf);
    } else if (bid < 96) {
        int id = bid - 48, mt = id % 12, kc = id / 12;
        stage_global(Xf, g_h1T[po], kc * 128, 128);
        gemm_tile(W_hh1, 512, mt * 128, kc * 128, 8, g_pHH1[kc], Ws, Xf);
    } else if (t > 0) {
        int id = bid - 96, mt = id % 4, kc = id / 4;   // kc in [0,12)
        stage_global(Xf, g_xr, kc * 128, 128);
        gemm_tile(RW, 1536, mt * 128, kc * 128, 8, g_pR[kc], Ws, Xf);
    }
}

// ------------------- kD: q/tq GEMMs (64 blocks) -------------------
__global__ void __launch_bounds__(256)
kD(const float* __restrict__ qW, const float* __restrict__ tqW, int t) {
    __shared__ float Ws[16 * 132];
    __shared__ float Xf[64 * 64];
    int bid = blockIdx.x;
    int pn = (t & 1) ^ 1;
    int mat = bid >> 5, id = bid & 31, mt = id & 3, kc = id >> 2;  // kc in [0,8), 64-row chunks
    stage_global(Xf, g_h1T[pn], kc * 64, 64);
    gemm_tile(mat ? tqW : qW, 512, mt * 128, kc * 64, 4,
              mat ? g_pTQ[kc] : g_pQ[kc], Ws, Xf);
}

// ------------------- kE: gate + q-combine + energies + softmax + ctxmix + actD(t-1) -------------------
__global__ void __launch_bounds__(1024)
kE(const float* __restrict__ context, const float* __restrict__ tcontext,
   const float* __restrict__ smask, const float* __restrict__ tmask,
   const float* __restrict__ av, const float* __restrict__ tav,
   const float* __restrict__ gW, const float* __restrict__ gb,
   const float* __restrict__ Rb, const int* __restrict__ tgt,
   const float* __restrict__ embt,
   float* __restrict__ go, float* __restrict__ attn, float* __restrict__ tattn,
   float* __restrict__ gatev, int t) {
    int bid = blockIdx.x, tid = threadIdx.x;
    int pn = (t & 1) ^ 1;

    if (bid >= 64) {   // actD for step t-1 (4 blocks x 1024 threads x 4 outputs)
        if (t > 0) {
            int id = bid - 64;
            for (int p = 0; p < 4; p++) {
                int i = id * 4096 + p * 1024 + tid;
                int u = i >> 6, b = i & 63;
                int j0 = 2 * u, j1 = 2 * u + 1;
                float r0 = Rb[j0], r1 = Rb[j1];
#pragma unroll
                for (int kc = 0; kc < 12; kc++) {
                    r0 += g_pR[kc][(size_t)j0 * 64 + b];
                    r1 += g_pR[kc][(size_t)j1 * 64 + b];
                }
                go[(size_t)(t - 1) * 16384 + b * 256 + u] = fmaxf(r0, r1);
            }
        }
        return;
    }

    int b = bid;
    __shared__ float qs[512], tqs[512], vs[512], tvs[512];
    __shared__ float es[SLEN], tes[56], sred[32];
    __shared__ float cp0[512], cp1[512], tp0[512], tp1[512];
    int warp = tid >> 5, lane = tid & 31;

    // ---- staging (tid < 512): q/tq combine, v, copies, gate partial ----
    float gv = 0.f;
    if (tid < 512) {
        int d = tid;
        float s1 = 0.f, s2 = 0.f;
#pragma unroll
        for (int kc = 0; kc < 8; kc++) {
            s1 += g_pQ[kc][(size_t)d * 64 + b];
            s2 += g_pTQ[kc][(size_t)d * 64 + b];
        }
        qs[d] = s1; tqs[d] = s2;
        vs[d] = av[d]; tvs[d] = tav[d];
        float h1v = g_h1T[pn][(size_t)d * 64 + b];
        g_xr[(size_t)d * 64 + b] = g_x0[(size_t)d * 64 + b];  // emb(t) for readout
        gv = h1v * gW[d];
    }
#pragma unroll
    for (int o = 16; o; o >>= 1) gv += __shfl_xor_sync(0xffffffffu, gv, o);
    if (lane == 0) sred[warp] = gv;
    __syncthreads();
    float gsum = 0.f;
#pragma unroll
    for (int w = 0; w < 32; w++) gsum += sred[w];
    float gate = sigmoidf_(gsum + gb[0]);
    if (tid == 0) gatev[t * 64 + b] = gate;
    __syncthreads();

    // ---- energies (32 warps) ----
    for (int l = warp; l < SLEN; l += 32) {
        const float* pr = g_pre + ((size_t)b * SLEN + l) * 512;
        float e = 0.f;
#pragma unroll
        for (int c = 0; c < 4; c++) {
            int a = c * 128 + lane * 4;
            float4 p = *(const float4*)(pr + a);
            float4 q4 = *(const float4*)(qs + a);
            float4 v4 = *(const float4*)(vs + a);
            e += tanh_fast(p.x + q4.x) * v4.x;
            e += tanh_fast(p.y + q4.y) * v4.y;
            e += tanh_fast(p.z + q4.z) * v4.z;
            e += tanh_fast(p.w + q4.w) * v4.w;
        }
#pragma unroll
        for (int o = 16; o; o >>= 1) e += __shfl_xor_sync(0xffffffffu, e, o);
        if (lane == 0) es[l] = (smask[b * SLEN + l] > 0.5f) ? -1e6f : e;
    }
    for (int l = warp; l < KLEN; l += 32) {
        const float* pr = g_tpre + ((size_t)b * KLEN + l) * 512;
        float e = 0.f;
#pragma unroll
        for (int c = 0; c < 4; c++) {
            int a = c * 128 + lane * 4;
            float4 p = *(const float4*)(pr + a);
            float4 q4 = *(const float4*)(tqs + a);
            float4 v4 = *(const float4*)(tvs + a);
            e += tanh_fast(p.x + q4.x) * v4.x;
            e += tanh_fast(p.y + q4.y) * v4.y;
            e += tanh_fast(p.z + q4.z) * v4.z;
            e += tanh_fast(p.w + q4.w) * v4.w;
        }
#pragma unroll
        for (int o = 16; o; o >>= 1) e += __shfl_xor_sync(0xffffffffu, e, o);
        if (lane == 0) tes[l] = (tmask[b * KLEN + l] > 0.5f) ? -1e6f : e;
    }
    __syncthreads();

    // ---- softmax src (400) ----
    float m = (tid < SLEN) ? es[tid] : -3.4e38f;
#pragma unroll
    for (int o = 16; o; o >>= 1) m = fmaxf(m, __shfl_xor_sync(0xffffffffu, m, o));
    if (lane == 0) sred[warp] = m;
    __syncthreads();
    float bm = sred[0];
#pragma unroll
    for (int w = 1; w < 32; w++) bm = fmaxf(bm, sred[w]);
    __syncthreads();
    float ex = (tid < SLEN) ? __expf(es[tid] - bm) : 0.f;
    float ssum = ex;
#pragma unroll
    for (int o = 16; o; o >>= 1) ssum += __shfl_xor_sync(0xffffffffu, ssum, o);
    if (lane == 0) sred[warp] = ssum;
    __syncthreads();
    float bs = 0.f;
#pragma unroll
    for (int w = 0; w < 32; w++) bs += sred[w];
    float inv = 1.0f / bs;
    __syncthreads();
    if (tid < SLEN) {
        float pv = ex * inv;
        es[tid] = pv;
        attn[(size_t)t * 64 * SLEN + (size_t)b * SLEN + tid] = pv;
    }
    __syncthreads();

    // ---- softmax topic (50) ----
    float tm_ = (tid < KLEN) ? tes[tid] : -3.4e38f;
#pragma unroll
    for (int o = 16; o; o >>= 1) tm_ = fmaxf(tm_, __shfl_xor_sync(0xffffffffu, tm_, o));
    if (lane == 0) sred[warp] = tm_;
    __syncthreads();
    float tbm = sred[0];
#pragma unroll
    for (int w = 1; w < 32; w++) tbm = fmaxf(tbm, sred[w]);
    __syncthreads();
    float tex = (tid < KLEN) ? __expf(tes[tid] - tbm) : 0.f;
    float tssum = tex;
#pragma unroll
    for (int o = 16; o; o >>= 1) tssum += __shfl_xor_sync(0xffffffffu, tssum, o);
    if (lane == 0) sred[warp] = tssum;
    __syncthreads();
    float tbs = 0.f;
#pragma unroll
    for (int w = 0; w < 32; w++) tbs += sred[w];
    float tinv = 1.0f / tbs;
    __syncthreads();
    if (tid < KLEN) {
        float pv = tex * tinv;
        tes[tid] = pv;
        tattn[(size_t)t * 64 * KLEN + (size_t)b * KLEN + tid] = pv;
    }
    __syncthreads();

    // ---- ctxmix: two halves of l-range, combined via smem ----
    {
        int half = tid >> 9, d = tid & 511;
        const float* cb = context + (size_t)b * 512 + d;
        float c = 0.f;
        int l0 = half * 200, l1 = l0 + 200;
#pragma unroll 8
        for (int l = l0; l < l1; l++) c += es[l] * cb[(size_t)l * 64 * 512];
        (half ? cp1 : cp0)[d] = c;
        const float* tcb = tcontext + (size_t)b * 512 + d;
        float tc = 0.f;
        int tl0 = half * 25, tl1 = tl0 + 25;
#pragma unroll
        for (int l = tl0; l < tl1; l++) tc += tes[l] * tcb[(size_t)l * 64 * 512];
        (half ? tp1 : tp0)[d] = tc;
    }
    __syncthreads();
    if (tid < 512) {
        int d = tid;
        float mixv = gate * (cp0[d] + cp1[d]) + (1.f - gate) * (tp0[d] + tp1[d]);
        g_x0[(size_t)(512 + d) * 64 + b] = mixv;     // mix for next GRU0 input
        g_xr[(size_t)(1024 + d) * 64 + b] = mixv;    // mix for this step's readout
        if (t + 1 < TSTEPS) {
            int tok = tgt[(t + 1) * 64 + b];
            g_x0[(size_t)d * 64 + b] = embt[(size_t)tok * 512 + d];
        }
    }
}

// ------------------- kR: readout GEMM for t=49 -------------------
__global__ void __launch_bounds__(256)
kR(const float* __restrict__ RW) {
    __shared__ float Ws[16 * 132];
    __shared__ float Xf[128 * 64];
    int bid = blockIdx.x;
    int mt = bid % 4, kc = bid / 4;
    stage_global(Xf, g_xr, kc * 128, 128);
    gemm_tile(RW, 1536, mt * 128, kc * 128, 8, g_pR[kc], Ws, Xf);
}

// ------------------- kFin: actD(49) + final state copies -------------------
__global__ void __launch_bounds__(256)
kFin(const float* __restrict__ Rb, float* __restrict__ go,
     float* __restrict__ hf, float* __restrict__ mixf) {
    int bid = blockIdx.x, tid = threadIdx.x;
    if (bid < 4) {
        for (int p = 0; p < 16; p++) {
            int i = bid * 4096 + p * 256 + tid;
            int u = i >> 6, b = i & 63;
            int j0 = 2 * u, j1 = 2 * u + 1;
            float r0 = Rb[j0], r1 = Rb[j1];
#pragma unroll
            for (int kc = 0; kc < 12; kc++) {
                r0 += g_pR[kc][(size_t)j0 * 64 + b];
                r1 += g_pR[kc][(size_t)j1 * 64 + b];
            }
            go[(size_t)49 * 16384 + b * 256 + u] = fmaxf(r0, r1);
        }
    } else {
        for (int i = (bid - 4) * 256 + tid; i < 32768; i += 16 * 256) {
            int b = i >> 9, d = i & 511;
            hf[i] = g_h0T[0][d * 64 + b];           // after t=49 (po=1) new state is index 0
            hf[32768 + i] = g_h1T[0][d * 64 + b];
            mixf[i] = g_x0[(512 + d) * 64 + b];
        }
    }
}

// ------------------- launch -------------------
extern "C" void kernel_launch(void* const* d_in, const int* in_sizes, int n_in,
                              void* d_out, int out_size) {
    const int*   tgt      = (const int*)d_in[0];
    const float* hidden   = (const float*)d_in[1];
    const float* context  = (const float*)d_in[2];
    const float* smask    = (const float*)d_in[3];
    const float* tcontext = (const float*)d_in[4];
    const float* tmask    = (const float*)d_in[5];
    const float* mix_init = (const float*)d_in[6];
    const float* embt     = (const float*)d_in[7];
    const float* W_ih0    = (const float*)d_in[8];
    const float* W_hh0    = (const float*)d_in[9];
    const float* b_ih0    = (const float*)d_in[10];
    const float* b_hh0    = (const float*)d_in[11];
    const float* W_ih1    = (const float*)d_in[12];
    const float* W_hh1    = (const float*)d_in[13];
    const float* b_ih1    = (const float*)d_in[14];
    const float* b_hh1    = (const float*)d_in[15];
    const float* preW     = (const float*)d_in[16];
    const float* preB     = (const float*)d_in[17];
    const float* qW       = (const float*)d_in[18];
    const float* av       = (const float*)d_in[19];
    const float* tpreW    = (const float*)d_in[20];
    const float* tpreB    = (const float*)d_in[21];
    const float* tqW      = (const float*)d_in[22];
    const float* tav      = (const float*)d_in[23];
    const float* RW       = (const float*)d_in[24];
    const float* Rb       = (const float*)d_in[25];
    const float* gW       = (const float*)d_in[26];
    const float* gb       = (const float*)d_in[27];

    float* out   = (float*)d_out;
    float* go    = out;                                   // [T,B,256]
    float* hf    = go + (size_t)TSTEPS * 64 * 256;        // [2,B,D]
    float* attn  = hf + 2 * 64 * 512;                     // [T,B,S]
    float* tattn = attn + (size_t)TSTEPS * 64 * SLEN;     // [T,B,K]
    float* mixf  = tattn + (size_t)TSTEPS * 64 * KLEN;    // [B,D]
    float* gatev = mixf + 64 * 512;                       // [T,B,1]

    kInit<<<128, 256>>>(tgt, hidden, mix_init, embt);
    pre_gemm<<<dim3(SLEN + KLEN, 4), 256>>>(context, tcontext, preW, preB, tpreW, tpreB);

    for (int t = 0; t < TSTEPS; t++) {
        kA<<<144, 256>>>(W_ih0, W_hh0, t);
        kAct0<<<32, 256>>>(b_ih0, b_hh0, t);
        kB<<<144, 256>>>(W_ih1, W_hh1, RW, t);
        kAct1<<<32, 256>>>(b_ih1, b_hh1, t);
        kD<<<64, 256>>>(qW, tqW, t);
        kE<<<68, 1024>>>(context, tcontext, smask, tmask, av, tav, gW, gb, Rb,
                         tgt, embt, go, attn, tattn, gatev, t);
    }
    kR<<<48, 256>>>(RW);
    kFin<<<20, 256>>>(Rb, go, hf, mixf);
}